// round 6
// baseline (speedup 1.0000x reference)
#include <cuda_runtime.h>
#include <cuda_bf16.h>
#include <cstdint>
#include <cfloat>

#define NS 16384
#define NQ 16384
#define DIM 64
#define NC 64
#define NTILES (NS / 128)
#define DELTA 2e-3f

// ---------------- device scratch (no allocs allowed) ----------------
__device__ float g_sq_s[NS];
__device__ float g_sq_q[NQ];
__device__ int   g_lab[NS];
__device__ __align__(16) __nv_bfloat16 g_Shi[NS * DIM];
__device__ __align__(16) __nv_bfloat16 g_Slo[NS * DIM];
__device__ __align__(16) __nv_bfloat16 g_Qhi[NQ * DIM];
__device__ __align__(16) __nv_bfloat16 g_Qlo[NQ * DIM];
__device__ int g_flag_count;
__device__ int g_flag_q[NQ];

// ---------------- helpers ----------------
__device__ __forceinline__ uint32_t smem_u32(const void* p) {
    uint32_t a;
    asm("{ .reg .u64 t; cvta.to.shared.u64 t, %1; cvt.u32.u64 %0, t; }" : "=r"(a) : "l"(p));
    return a;
}

__device__ __forceinline__ void ldsm4(uint32_t* r, uint32_t addr) {
    asm volatile("ldmatrix.sync.aligned.m8n8.x4.shared.b16 {%0,%1,%2,%3}, [%4];"
                 : "=r"(r[0]), "=r"(r[1]), "=r"(r[2]), "=r"(r[3]) : "r"(addr));
}

__device__ __forceinline__ void mma16816(float* d, const uint32_t* a, const uint32_t* b) {
    asm volatile("mma.sync.aligned.m16n8k16.row.col.f32.bf16.bf16.f32 "
                 "{%0,%1,%2,%3}, {%4,%5,%6,%7}, {%8,%9}, {%0,%1,%2,%3};"
                 : "+f"(d[0]), "+f"(d[1]), "+f"(d[2]), "+f"(d[3])
                 : "r"(a[0]), "r"(a[1]), "r"(a[2]), "r"(a[3]), "r"(b[0]), "r"(b[1]));
}

// ---------------- prep ----------------
__global__ __launch_bounds__(256) void prep_kernel(const float* __restrict__ S,
                                                   const float* __restrict__ Q,
                                                   const float* __restrict__ OH) {
    int row = blockIdx.x * blockDim.x + threadIdx.x;
    if (row == 0) g_flag_count = 0;
    if (row >= NS) return;
    {
        const float4* s4 = (const float4*)(S + (size_t)row * DIM);
        float acc = 0.f;
        #pragma unroll
        for (int i = 0; i < DIM / 4; i++) {
            float4 v = s4[i];
            acc += v.x * v.x + v.y * v.y + v.z * v.z + v.w * v.w;
        }
        g_sq_s[row] = acc;
    }
    {
        const float4* q4 = (const float4*)(Q + (size_t)row * DIM);
        float acc = 0.f;
        #pragma unroll
        for (int i = 0; i < DIM / 4; i++) {
            float4 v = q4[i];
            acc += v.x * v.x + v.y * v.y + v.z * v.z + v.w * v.w;
        }
        g_sq_q[row] = acc;
    }
    #pragma unroll 8
    for (int k = 0; k < DIM; k++) {
        float x = S[(size_t)row * DIM + k];
        __nv_bfloat16 h = __float2bfloat16_rn(x);
        g_Shi[(size_t)row * DIM + k] = h;
        g_Slo[(size_t)row * DIM + k] = __float2bfloat16_rn(x - __bfloat162float(h));
        float y = Q[(size_t)row * DIM + k];
        __nv_bfloat16 hq = __float2bfloat16_rn(y);
        g_Qhi[(size_t)row * DIM + k] = hq;
        g_Qlo[(size_t)row * DIM + k] = __float2bfloat16_rn(y - __bfloat162float(hq));
    }
    {
        const float* oh = OH + (size_t)row * NC;
        float best = oh[0];
        int bi = 0;
        #pragma unroll 8
        for (int c = 1; c < NC; c++) {
            float v = oh[c];
            if (v > best) { best = v; bi = c; }
        }
        g_lab[row] = bi;
    }
}

// ---------------- main HMMA kernel ----------------
// SMEM byte offsets (dynamic)
#define OFF_QHI  0                 // 16 KB, Q hi, 128 rows x 128B, swizzled
#define OFF_QLO  16384             // 16 KB
#define OFF_B    32768             // 2 bufs x (Shi 16K + Slo 16K) = 64 KB
#define OFF_SQS  98304             // 64 KB: all 16384 ||s||^2
#define OFF_PM1  163840            // 256 f
#define OFF_PM2  164864
#define OFF_PI1  165888
#define OFF_LAB  166912            // 128 ints
#define SMEM_SZ  167424

__device__ __forceinline__ void ldB(uint4* pf, int t, int tid) {
    const uint4* hi = (const uint4*)g_Shi + (size_t)t * 1024;
    const uint4* lo = (const uint4*)g_Slo + (size_t)t * 1024;
    #pragma unroll
    for (int i = 0; i < 4; i++) pf[i]     = hi[tid + i * 256];
    #pragma unroll
    for (int i = 0; i < 4; i++) pf[4 + i] = lo[tid + i * 256];
}

__device__ __forceinline__ void stB(char* smem, const uint4* pf, int buf, int tid) {
    char* bhi = smem + OFF_B + buf * 32768;
    char* blo = bhi + 16384;
    #pragma unroll
    for (int i = 0; i < 4; i++) {
        uint32_t off = (uint32_t)(tid + i * 256) * 16;
        uint32_t sw = off ^ ((off >> 3) & 0x70);
        *(uint4*)(bhi + sw) = pf[i];
        *(uint4*)(blo + sw) = pf[4 + i];
    }
}

__global__ __launch_bounds__(256, 1) void knn_mma_kernel(float* __restrict__ out) {
    extern __shared__ __align__(1024) char smem[];
    const uint32_t sbase = smem_u32(smem);
    const int tid  = threadIdx.x;
    const int lane = tid & 31;
    const int w    = tid >> 5;
    const int wm   = w & 3;          // query strip: rows [wm*32, wm*32+32)
    const int wn   = w >> 2;         // support half: cols [wn*64, wn*64+64)
    const int g    = lane >> 2;
    const int tig  = lane & 3;
    const int qbase = blockIdx.x * 128;
    float* sqs_sm = (float*)(smem + OFF_SQS);

    uint4 pf[8];

    // -- Q hi/lo tiles, swizzled (128 rows x 128B each) --
    {
        const uint4* hi = (const uint4*)g_Qhi + (size_t)qbase * 8;  // 64 bf16 = 8 uint4/row
        const uint4* lo = (const uint4*)g_Qlo + (size_t)qbase * 8;
        char* qh = smem + OFF_QHI;
        char* ql = smem + OFF_QLO;
        #pragma unroll
        for (int i = 0; i < 4; i++) {
            uint32_t off = (uint32_t)(tid + i * 256) * 16;
            uint32_t sw = off ^ ((off >> 3) & 0x70);
            *(uint4*)(qh + sw) = hi[tid + i * 256];
            *(uint4*)(ql + sw) = lo[tid + i * 256];
        }
    }
    // -- all ||s||^2 into smem --
    {
        const float4* src = (const float4*)g_sq_s;
        float4* d = (float4*)sqs_sm;
        #pragma unroll
        for (int i = 0; i < 16; i++) d[tid + i * 256] = src[tid + i * 256];
    }
    // -- S tile 0 --
    ldB(pf, 0, tid);
    stB(smem, pf, 0, tid);
    __syncthreads();

    // ldmatrix per-thread address components
    const uint32_t xorv  = (uint32_t)(lane & 7) * 16;
    const uint32_t a_kb  = (lane & 16) ? 16u : 0u;
    const uint32_t b_kb  = (lane & 8)  ? 16u : 0u;
    const int rowA = wm * 32 + (lane & 15);
    const int rowB = wn * 64 + ((lane & 16) ? 8 : 0) + (lane & 7);
    const uint32_t aQhi = sbase + OFF_QHI + (uint32_t)rowA * 128;
    const uint32_t aQlo = sbase + OFF_QLO + (uint32_t)rowA * 128;

    float m1[4], m2[4];
    int   i1[4];
    #pragma unroll
    for (int s = 0; s < 4; s++) { m1[s] = FLT_MAX; m2[s] = FLT_MAX; i1[s] = 0; }

    for (int t = 0; t < NTILES; t++) {
        const int buf = t & 1;
        if (t < NTILES - 1) ldB(pf, t + 1, tid);

        float acc[2][8][4];
        #pragma unroll
        for (int mt = 0; mt < 2; mt++)
            #pragma unroll
            for (int nt = 0; nt < 8; nt++)
                #pragma unroll
                for (int j = 0; j < 4; j++) acc[mt][nt][j] = 0.f;

        const uint32_t bB = sbase + OFF_B + (uint32_t)buf * 32768 + (uint32_t)rowB * 128;

        #pragma unroll
        for (int ks = 0; ks < 4; ks++) {
            const uint32_t ak = ((uint32_t)ks * 32 + a_kb) ^ xorv;
            const uint32_t bk = ((uint32_t)ks * 32 + b_kb) ^ xorv;
            uint32_t Ah[2][4], Al[2][4];
            ldsm4(Ah[0], aQhi + ak);
            ldsm4(Ah[1], aQhi + 2048 + ak);
            ldsm4(Al[0], aQlo + ak);
            ldsm4(Al[1], aQlo + 2048 + ak);
            uint32_t Bh[4][4], Bl[4][4];
            #pragma unroll
            for (int p = 0; p < 4; p++) {
                ldsm4(Bh[p], bB + (uint32_t)p * 2048 + bk);
                ldsm4(Bl[p], bB + 16384 + (uint32_t)p * 2048 + bk);
            }
            #pragma unroll
            for (int mt = 0; mt < 2; mt++)
                #pragma unroll
                for (int nt = 0; nt < 8; nt++) {
                    const uint32_t* bh = &Bh[nt >> 1][(nt & 1) * 2];
                    const uint32_t* bl = &Bl[nt >> 1][(nt & 1) * 2];
                    mma16816(acc[mt][nt], Ah[mt], bh);
                    mma16816(acc[mt][nt], Ah[mt], bl);
                    mma16816(acc[mt][nt], Al[mt], bh);
                }
        }

        // fused epilogue: d2' = ||s||^2 - 2*cross; per-thread top-2 per query row
        const int sb = t * 128 + wn * 64;
        const float* sq = sqs_sm + sb;
        #pragma unroll
        for (int nt = 0; nt < 8; nt++) {
            float2 s2 = *(const float2*)(sq + nt * 8 + 2 * tig);
            int idx0 = sb + nt * 8 + 2 * tig;
            #pragma unroll
            for (int mt = 0; mt < 2; mt++)
                #pragma unroll
                for (int rh = 0; rh < 2; rh++) {
                    const int s = mt * 2 + rh;
                    float v0 = fmaf(-2.f, acc[mt][nt][rh * 2 + 0], s2.x);
                    float v1 = fmaf(-2.f, acc[mt][nt][rh * 2 + 1], s2.y);
                    if (v0 < m1[s])      { m2[s] = m1[s]; m1[s] = v0; i1[s] = idx0; }
                    else if (v0 < m2[s]) { m2[s] = v0; }
                    if (v1 < m1[s])      { m2[s] = m1[s]; m1[s] = v1; i1[s] = idx0 + 1; }
                    else if (v1 < m2[s]) { m2[s] = v1; }
                }
        }

        if (t < NTILES - 1) stB(smem, pf, buf ^ 1, tid);
        __syncthreads();
    }

    // -- quad reduce (4 lanes share each row) then stash per column-half --
    float* pm1 = (float*)(smem + OFF_PM1);
    float* pm2 = (float*)(smem + OFF_PM2);
    int*   pi1 = (int*)(smem + OFF_PI1);
    int*   lab = (int*)(smem + OFF_LAB);

    #pragma unroll
    for (int s = 0; s < 4; s++) {
        float M1 = m1[s], M2 = m2[s];
        int   I1 = i1[s];
        #pragma unroll
        for (int off = 1; off <= 2; off <<= 1) {
            float o1 = __shfl_xor_sync(0xffffffffu, M1, off);
            float o2 = __shfl_xor_sync(0xffffffffu, M2, off);
            int   oi = __shfl_xor_sync(0xffffffffu, I1, off);
            if (o1 < M1 || (o1 == M1 && oi < I1)) { M2 = fminf(M1, o2); M1 = o1; I1 = oi; }
            else                                  { M2 = fminf(o1, M2); }
        }
        int row = wm * 32 + (s >> 1) * 16 + (s & 1) * 8 + g;
        if (tig == 0) {
            pm1[wn * 128 + row] = M1;
            pm2[wn * 128 + row] = M2;
            pi1[wn * 128 + row] = I1;
        }
    }
    __syncthreads();

    // -- merge the two column halves per query, flag narrow margins --
    if (tid < 128) {
        float am1 = pm1[tid], am2 = pm2[tid];  int ai = pi1[tid];
        float bm1 = pm1[tid + 128], bm2 = pm2[tid + 128]; int bi = pi1[tid + 128];
        float M1, M2; int I1;
        if (bm1 < am1 || (bm1 == am1 && bi < ai)) { M1 = bm1; I1 = bi; M2 = fminf(am1, bm2); }
        else                                      { M1 = am1; I1 = ai; M2 = fminf(bm1, am2); }
        if (M2 - M1 < DELTA) {
            int slot = atomicAdd(&g_flag_count, 1);
            g_flag_q[slot] = qbase + tid;
        }
        lab[tid] = g_lab[I1];
    }
    __syncthreads();

    // -- one-hot write: 128 rows x 64 cols --
    #pragma unroll
    for (int j = 0; j < 8; j++) {
        int gi = tid * 8 + j;
        int row = gi >> 4;
        int c4 = (gi & 15) * 4;
        int lb = lab[row];
        float4 v;
        v.x = (c4 + 0 == lb) ? 1.f : 0.f;
        v.y = (c4 + 1 == lb) ? 1.f : 0.f;
        v.z = (c4 + 2 == lb) ? 1.f : 0.f;
        v.w = (c4 + 3 == lb) ? 1.f : 0.f;
        *(float4*)(out + (size_t)(qbase + row) * NC + c4) = v;
    }
}

// ---------------- exact cleanup for flagged queries ----------------
__global__ __launch_bounds__(256) void cleanup_kernel(const float* __restrict__ S,
                                                      const float* __restrict__ Q,
                                                      float* __restrict__ out) {
    __shared__ float qrow[DIM];
    __shared__ float bd[256];
    __shared__ int   bix[256];
    const int tid = threadIdx.x;
    const int nflag = g_flag_count;
    for (int f = blockIdx.x; f < nflag; f += gridDim.x) {
        int q = g_flag_q[f];
        if (tid < DIM) qrow[tid] = Q[(size_t)q * DIM + tid];
        __syncthreads();
        float sqq = g_sq_q[q];
        float best = FLT_MAX;
        int bidx = 0;
        for (int s = tid; s < NS; s += 256) {
            const float* sr = S + (size_t)s * DIM;
            float acc = 0.f;
            #pragma unroll
            for (int k = 0; k < DIM; k++) acc = fmaf(qrow[k], sr[k], acc);
            float d2 = fmaf(-2.f, acc, sqq + g_sq_s[s]);
            if (d2 < best) { best = d2; bidx = s; }
        }
        bd[tid] = best; bix[tid] = bidx;
        __syncthreads();
        for (int off = 128; off > 0; off >>= 1) {
            if (tid < off) {
                float od = bd[tid + off]; int oi = bix[tid + off];
                if (od < bd[tid] || (od == bd[tid] && oi < bix[tid])) {
                    bd[tid] = od; bix[tid] = oi;
                }
            }
            __syncthreads();
        }
        int lb = g_lab[bix[0]];
        if (tid < NC) out[(size_t)q * NC + tid] = (tid == lb) ? 1.f : 0.f;
        __syncthreads();
    }
}

// ---------------- launch ----------------
extern "C" void kernel_launch(void* const* d_in, const int* in_sizes, int n_in,
                              void* d_out, int out_size) {
    const float* S  = (const float*)d_in[0];  // support_embeddings [NS, D]
    const float* Q  = (const float*)d_in[1];  // query_embeddings   [NQ, D]
    const float* OH = (const float*)d_in[2];  // support_labels_onehot [NS, NC]
    float* out = (float*)d_out;               // [NQ, NC] fp32

    static bool attr_set = false;
    if (!attr_set) {
        cudaFuncSetAttribute(knn_mma_kernel,
                             cudaFuncAttributeMaxDynamicSharedMemorySize, SMEM_SZ);
        attr_set = true;
    }

    prep_kernel<<<NS / 256, 256>>>(S, Q, OH);
    knn_mma_kernel<<<NQ / 128, 256, SMEM_SZ>>>(out);
    cleanup_kernel<<<128, 256>>>(S, Q, out);
}

// round 9
// speedup vs baseline: 1.1039x; 1.1039x over previous
#include <cuda_runtime.h>
#include <cuda_bf16.h>
#include <cstdint>
#include <cfloat>

#define NS 16384
#define NQ 16384
#define DIM 64
#define NC 64
#define NTILES (NS / 128)
#define DELTA 2e-3f

// ---------------- device scratch (no allocs allowed) ----------------
__device__ float g_sq_s[NS];
__device__ float g_sq_q[NQ];
__device__ int   g_lab[NS];
__device__ __align__(16) __nv_bfloat16 g_Shi[NS * DIM];
__device__ __align__(16) __nv_bfloat16 g_Slo[NS * DIM];
__device__ __align__(16) __nv_bfloat16 g_Qhi[NQ * DIM];
__device__ __align__(16) __nv_bfloat16 g_Qlo[NQ * DIM];
__device__ int g_flag_count;
__device__ int g_flag_q[NQ];

// ---------------- helpers ----------------
__device__ __forceinline__ uint32_t smem_u32(const void* p) {
    uint32_t a;
    asm("{ .reg .u64 t; cvta.to.shared.u64 t, %1; cvt.u32.u64 %0, t; }" : "=r"(a) : "l"(p));
    return a;
}

__device__ __forceinline__ void ldsm4(uint32_t* r, uint32_t addr) {
    asm volatile("ldmatrix.sync.aligned.m8n8.x4.shared.b16 {%0,%1,%2,%3}, [%4];"
                 : "=r"(r[0]), "=r"(r[1]), "=r"(r[2]), "=r"(r[3]) : "r"(addr));
}

__device__ __forceinline__ void mma16816(float* d, const uint32_t* a, const uint32_t* b) {
    asm volatile("mma.sync.aligned.m16n8k16.row.col.f32.bf16.bf16.f32 "
                 "{%0,%1,%2,%3}, {%4,%5,%6,%7}, {%8,%9}, {%0,%1,%2,%3};"
                 : "+f"(d[0]), "+f"(d[1]), "+f"(d[2]), "+f"(d[3])
                 : "r"(a[0]), "r"(a[1]), "r"(a[2]), "r"(a[3]), "r"(b[0]), "r"(b[1]));
}

#define CP_ASYNC16(dst, src) \
    asm volatile("cp.async.cg.shared.global [%0], [%1], 16;" :: "r"(dst), "l"(src))
#define CP_COMMIT() asm volatile("cp.async.commit_group;" ::: "memory")
#define CP_WAIT1()  asm volatile("cp.async.wait_group 1;" ::: "memory")

// ---------------- prep (vectorized: 4 threads per row) ----------------
__global__ __launch_bounds__(256) void prep_kernel(const float* __restrict__ S,
                                                   const float* __restrict__ Q,
                                                   const float* __restrict__ OH) {
    int gid = blockIdx.x * blockDim.x + threadIdx.x;   // 65536 threads
    if (gid == 0) g_flag_count = 0;
    int row = gid >> 2;
    int seg = gid & 3;            // 16 dims per thread
    int kb  = seg * 16;

    float4 sv[4], qv[4];
    #pragma unroll
    for (int i = 0; i < 4; i++) {
        sv[i] = *(const float4*)(S + (size_t)row * DIM + kb + i * 4);
        qv[i] = *(const float4*)(Q + (size_t)row * DIM + kb + i * 4);
    }
    // split + pack: 16 bf16 = 2 uint4 per array
    uint32_t shi[8], slo[8], qhi[8], qlo[8];
    #pragma unroll
    for (int i = 0; i < 4; i++) {
        const float sx[4] = {sv[i].x, sv[i].y, sv[i].z, sv[i].w};
        const float qx[4] = {qv[i].x, qv[i].y, qv[i].z, qv[i].w};
        #pragma unroll
        for (int p = 0; p < 2; p++) {
            float s0 = sx[p * 2], s1 = sx[p * 2 + 1];
            __nv_bfloat16 h0 = __float2bfloat16_rn(s0), h1 = __float2bfloat16_rn(s1);
            __nv_bfloat16 l0 = __float2bfloat16_rn(s0 - __bfloat162float(h0));
            __nv_bfloat16 l1 = __float2bfloat16_rn(s1 - __bfloat162float(h1));
            shi[i * 2 + p] = (uint32_t)*(uint16_t*)&h0 | ((uint32_t)*(uint16_t*)&h1 << 16);
            slo[i * 2 + p] = (uint32_t)*(uint16_t*)&l0 | ((uint32_t)*(uint16_t*)&l1 << 16);
            float q0 = qx[p * 2], q1 = qx[p * 2 + 1];
            __nv_bfloat16 g0 = __float2bfloat16_rn(q0), g1 = __float2bfloat16_rn(q1);
            __nv_bfloat16 m0 = __float2bfloat16_rn(q0 - __bfloat162float(g0));
            __nv_bfloat16 m1 = __float2bfloat16_rn(q1 - __bfloat162float(g1));
            qhi[i * 2 + p] = (uint32_t)*(uint16_t*)&g0 | ((uint32_t)*(uint16_t*)&g1 << 16);
            qlo[i * 2 + p] = (uint32_t)*(uint16_t*)&m0 | ((uint32_t)*(uint16_t*)&m1 << 16);
        }
    }
    uint4* dsh = (uint4*)(g_Shi + (size_t)row * DIM + kb);
    uint4* dsl = (uint4*)(g_Slo + (size_t)row * DIM + kb);
    uint4* dqh = (uint4*)(g_Qhi + (size_t)row * DIM + kb);
    uint4* dql = (uint4*)(g_Qlo + (size_t)row * DIM + kb);
    dsh[0] = make_uint4(shi[0], shi[1], shi[2], shi[3]);
    dsh[1] = make_uint4(shi[4], shi[5], shi[6], shi[7]);
    dsl[0] = make_uint4(slo[0], slo[1], slo[2], slo[3]);
    dsl[1] = make_uint4(slo[4], slo[5], slo[6], slo[7]);
    dqh[0] = make_uint4(qhi[0], qhi[1], qhi[2], qhi[3]);
    dqh[1] = make_uint4(qhi[4], qhi[5], qhi[6], qhi[7]);
    dql[0] = make_uint4(qlo[0], qlo[1], qlo[2], qlo[3]);
    dql[1] = make_uint4(qlo[4], qlo[5], qlo[6], qlo[7]);

    // norms: partial then combine over the 4 lanes of this row
    float ps = 0.f, pq = 0.f;
    #pragma unroll
    for (int i = 0; i < 4; i++) {
        ps += sv[i].x * sv[i].x + sv[i].y * sv[i].y + sv[i].z * sv[i].z + sv[i].w * sv[i].w;
        pq += qv[i].x * qv[i].x + qv[i].y * qv[i].y + qv[i].z * qv[i].z + qv[i].w * qv[i].w;
    }
    #pragma unroll
    for (int off = 1; off <= 2; off <<= 1) {
        ps += __shfl_xor_sync(0xffffffffu, ps, off);
        pq += __shfl_xor_sync(0xffffffffu, pq, off);
    }
    // label: each lane scans 16 classes of the one-hot row
    float best = -1.f;
    int bi = kb;
    const float4* oh = (const float4*)(OH + (size_t)row * NC + kb);
    #pragma unroll
    for (int i = 0; i < 4; i++) {
        float4 v = oh[i];
        float vv[4] = {v.x, v.y, v.z, v.w};
        #pragma unroll
        for (int j = 0; j < 4; j++)
            if (vv[j] > best) { best = vv[j]; bi = kb + i * 4 + j; }
    }
    #pragma unroll
    for (int off = 1; off <= 2; off <<= 1) {
        float ob = __shfl_xor_sync(0xffffffffu, best, off);
        int   oi = __shfl_xor_sync(0xffffffffu, bi, off);
        if (ob > best || (ob == best && oi < bi)) { best = ob; bi = oi; }
    }
    if (seg == 0) {
        g_sq_s[row] = ps;
        g_sq_q[row] = pq;
        g_lab[row]  = bi;
    }
}

// ---------------- main HMMA kernel (512 threads, 16 warps) ----------------
#define OFF_QHI  0                 // 16 KB
#define OFF_QLO  16384             // 16 KB
#define OFF_B    32768             // 2 bufs x (hi 16K + lo 16K) = 64 KB
#define OFF_SQS  98304             // 64 KB
#define OFF_PM1  163840            // 512 f
#define OFF_PM2  165888
#define OFF_PI1  167936
#define OFF_LAB  169984            // 128 ints
#define SMEM_SZ  170496

__device__ __forceinline__ void issueS(uint32_t sbase, int t, int buf, int tid) {
    const char* srcHi = (const char*)g_Shi + (size_t)t * 16384;
    const char* srcLo = (const char*)g_Slo + (size_t)t * 16384;
    uint32_t dhi = sbase + OFF_B + (uint32_t)buf * 32768;
    #pragma unroll
    for (int i = 0; i < 2; i++) {
        uint32_t off = (uint32_t)(tid + i * 512) * 16;
        uint32_t sw = off ^ ((off >> 3) & 0x70);
        CP_ASYNC16(dhi + sw, srcHi + off);
        CP_ASYNC16(dhi + 16384 + sw, srcLo + off);
    }
}

__global__ __launch_bounds__(512, 1) void knn_mma_kernel(float* __restrict__ out) {
    extern __shared__ __align__(1024) char smem[];
    const uint32_t sbase = smem_u32(smem);
    const int tid  = threadIdx.x;
    const int lane = tid & 31;
    const int w    = tid >> 5;
    const int wm   = w & 3;          // query strip: rows [wm*32, +32)
    const int wn   = w >> 2;         // support strip: cols [wn*32, +32)
    const int g    = lane >> 2;
    const int tig  = lane & 3;
    const int qbase = blockIdx.x * 128;
    float* sqs_sm = (float*)(smem + OFF_SQS);

    // -- Q hi/lo tiles, swizzled --
    {
        const uint4* hi = (const uint4*)g_Qhi + (size_t)qbase * 8;
        const uint4* lo = (const uint4*)g_Qlo + (size_t)qbase * 8;
        char* qh = smem + OFF_QHI;
        char* ql = smem + OFF_QLO;
        #pragma unroll
        for (int i = 0; i < 2; i++) {
            uint32_t off = (uint32_t)(tid + i * 512) * 16;
            uint32_t sw = off ^ ((off >> 3) & 0x70);
            *(uint4*)(qh + sw) = hi[tid + i * 512];
            *(uint4*)(ql + sw) = lo[tid + i * 512];
        }
    }
    // -- all ||s||^2 into smem --
    {
        const float4* src = (const float4*)g_sq_s;
        float4* d = (float4*)sqs_sm;
        #pragma unroll
        for (int i = 0; i < 8; i++) d[tid + i * 512] = src[tid + i * 512];
    }
    // -- prologue: async-load tiles 0 and 1 --
    issueS(sbase, 0, 0, tid);
    CP_COMMIT();
    issueS(sbase, 1, 1, tid);
    CP_COMMIT();

    const uint32_t xorv = (uint32_t)(lane & 7) * 16;
    const uint32_t a_kb = (lane & 16) ? 16u : 0u;
    const uint32_t b_kb = (lane & 8)  ? 16u : 0u;
    const int rowA = wm * 32 + (lane & 15);
    const int rowB = wn * 32 + ((lane & 16) ? 8 : 0) + (lane & 7);
    const uint32_t aQhi = sbase + OFF_QHI + (uint32_t)rowA * 128;
    const uint32_t aQlo = sbase + OFF_QLO + (uint32_t)rowA * 128;

    float m1[4], m2[4];
    int   i1[4];
    #pragma unroll
    for (int s = 0; s < 4; s++) { m1[s] = FLT_MAX; m2[s] = FLT_MAX; i1[s] = 0; }

    for (int t = 0; t < NTILES; t++) {
        const int buf = t & 1;
        CP_WAIT1();
        __syncthreads();

        float acc[2][4][4];
        #pragma unroll
        for (int mt = 0; mt < 2; mt++)
            #pragma unroll
            for (int nt = 0; nt < 4; nt++)
                #pragma unroll
                for (int j = 0; j < 4; j++) acc[mt][nt][j] = 0.f;

        const uint32_t bB = sbase + OFF_B + (uint32_t)buf * 32768 + (uint32_t)rowB * 128;

        #pragma unroll
        for (int ks = 0; ks < 4; ks++) {
            const uint32_t ak = ((uint32_t)ks * 32 + a_kb) ^ xorv;
            const uint32_t bk = ((uint32_t)ks * 32 + b_kb) ^ xorv;
            uint32_t Ah[2][4], Al[2][4];
            ldsm4(Ah[0], aQhi + ak);
            ldsm4(Ah[1], aQhi + 2048 + ak);
            ldsm4(Al[0], aQlo + ak);
            ldsm4(Al[1], aQlo + 2048 + ak);
            uint32_t Bh[2][4], Bl[2][4];
            #pragma unroll
            for (int p = 0; p < 2; p++) {
                ldsm4(Bh[p], bB + (uint32_t)p * 2048 + bk);
                ldsm4(Bl[p], bB + 16384 + (uint32_t)p * 2048 + bk);
            }
            #pragma unroll
            for (int mt = 0; mt < 2; mt++)
                #pragma unroll
                for (int nt = 0; nt < 4; nt++) {
                    const uint32_t* bh = &Bh[nt >> 1][(nt & 1) * 2];
                    const uint32_t* bl = &Bl[nt >> 1][(nt & 1) * 2];
                    mma16816(acc[mt][nt], Ah[mt], bh);
                    mma16816(acc[mt][nt], Ah[mt], bl);
                    mma16816(acc[mt][nt], Al[mt], bh);
                }
        }

        // fused epilogue: d2' = ||s||^2 - 2*cross; per-thread top-2 per query row
        const int sb = t * 128 + wn * 32;
        const float* sq = sqs_sm + sb;
        #pragma unroll
        for (int nt = 0; nt < 4; nt++) {
            float2 s2 = *(const float2*)(sq + nt * 8 + 2 * tig);
            int idx0 = sb + nt * 8 + 2 * tig;
            #pragma unroll
            for (int mt = 0; mt < 2; mt++)
                #pragma unroll
                for (int rh = 0; rh < 2; rh++) {
                    const int s = mt * 2 + rh;
                    float v0 = fmaf(-2.f, acc[mt][nt][rh * 2 + 0], s2.x);
                    float v1 = fmaf(-2.f, acc[mt][nt][rh * 2 + 1], s2.y);
                    if (v0 < m1[s])      { m2[s] = m1[s]; m1[s] = v0; i1[s] = idx0; }
                    else if (v0 < m2[s]) { m2[s] = v0; }
                    if (v1 < m1[s])      { m2[s] = m1[s]; m1[s] = v1; i1[s] = idx0 + 1; }
                    else if (v1 < m2[s]) { m2[s] = v1; }
                }
        }

        __syncthreads();
        if (t + 2 < NTILES) issueS(sbase, t + 2, buf, tid);
        CP_COMMIT();
    }

    // -- quad reduce (4 lanes share each row), stash per support strip --
    float* pm1 = (float*)(smem + OFF_PM1);
    float* pm2 = (float*)(smem + OFF_PM2);
    int*   pi1 = (int*)(smem + OFF_PI1);
    int*   lab = (int*)(smem + OFF_LAB);

    #pragma unroll
    for (int s = 0; s < 4; s++) {
        float M1 = m1[s], M2 = m2[s];
        int   I1 = i1[s];
        #pragma unroll
        for (int off = 1; off <= 2; off <<= 1) {
            float o1 = __shfl_xor_sync(0xffffffffu, M1, off);
            float o2 = __shfl_xor_sync(0xffffffffu, M2, off);
            int   oi = __shfl_xor_sync(0xffffffffu, I1, off);
            if (o1 < M1 || (o1 == M1 && oi < I1)) { M2 = fminf(M1, o2); M1 = o1; I1 = oi; }
            else                                  { M2 = fminf(o1, M2); }
        }
        int row = wm * 32 + (s >> 1) * 16 + (s & 1) * 8 + g;
        if (tig == 0) {
            pm1[wn * 128 + row] = M1;
            pm2[wn * 128 + row] = M2;
            pi1[wn * 128 + row] = I1;
        }
    }
    __syncthreads();

    // -- merge the 4 support strips per query, flag narrow margins --
    if (tid < 128) {
        float M1 = FLT_MAX, M2 = FLT_MAX;
        int I1 = 0;
        #pragma unroll
        for (int sn = 0; sn < 4; sn++) {
            float a1 = pm1[sn * 128 + tid];
            float a2 = pm2[sn * 128 + tid];
            int   ai = pi1[sn * 128 + tid];
            if (a1 < M1 || (a1 == M1 && ai < I1)) { M2 = fminf(M1, a2); M1 = a1; I1 = ai; }
            else                                  { M2 = fminf(M2, a1); }
        }
        if (M2 - M1 < DELTA) {
            int slot = atomicAdd(&g_flag_count, 1);
            g_flag_q[slot] = qbase + tid;
        }
        lab[tid] = g_lab[I1];
    }
    __syncthreads();

    // -- one-hot write: 128 rows x 64 cols --
    #pragma unroll
    for (int j = 0; j < 4; j++) {
        int gi = tid * 4 + j;
        int row = gi >> 4;
        int c4 = (gi & 15) * 4;
        int lb = lab[row];
        float4 v;
        v.x = (c4 + 0 == lb) ? 1.f : 0.f;
        v.y = (c4 + 1 == lb) ? 1.f : 0.f;
        v.z = (c4 + 2 == lb) ? 1.f : 0.f;
        v.w = (c4 + 3 == lb) ? 1.f : 0.f;
        *(float4*)(out + (size_t)(qbase + row) * NC + c4) = v;
    }
}

// ---------------- exact cleanup for flagged queries ----------------
__global__ __launch_bounds__(256) void cleanup_kernel(const float* __restrict__ S,
                                                      const float* __restrict__ Q,
                                                      float* __restrict__ out) {
    __shared__ float qrow[DIM];
    __shared__ float bd[256];
    __shared__ int   bix[256];
    const int tid = threadIdx.x;
    const int nflag = g_flag_count;
    for (int f = blockIdx.x; f < nflag; f += gridDim.x) {
        int q = g_flag_q[f];
        if (tid < DIM) qrow[tid] = Q[(size_t)q * DIM + tid];
        __syncthreads();
        float sqq = g_sq_q[q];
        float best = FLT_MAX;
        int bidx = 0;
        for (int s = tid; s < NS; s += 256) {
            const float* sr = S + (size_t)s * DIM;
            float acc = 0.f;
            #pragma unroll
            for (int k = 0; k < DIM; k++) acc = fmaf(qrow[k], sr[k], acc);
            float d2 = fmaf(-2.f, acc, sqq + g_sq_s[s]);
            if (d2 < best) { best = d2; bidx = s; }
        }
        bd[tid] = best; bix[tid] = bidx;
        __syncthreads();
        for (int off = 128; off > 0; off >>= 1) {
            if (tid < off) {
                float od = bd[tid + off]; int oi = bix[tid + off];
                if (od < bd[tid] || (od == bd[tid] && oi < bix[tid])) {
                    bd[tid] = od; bix[tid] = oi;
                }
            }
            __syncthreads();
        }
        int lb = g_lab[bix[0]];
        if (tid < NC) out[(size_t)q * NC + tid] = (tid == lb) ? 1.f : 0.f;
        __syncthreads();
    }
}

// ---------------- launch ----------------
extern "C" void kernel_launch(void* const* d_in, const int* in_sizes, int n_in,
                              void* d_out, int out_size) {
    const float* S  = (const float*)d_in[0];
    const float* Q  = (const float*)d_in[1];
    const float* OH = (const float*)d_in[2];
    float* out = (float*)d_out;

    static bool attr_set = false;
    if (!attr_set) {
        cudaFuncSetAttribute(knn_mma_kernel,
                             cudaFuncAttributeMaxDynamicSharedMemorySize, SMEM_SZ);
        attr_set = true;
    }

    prep_kernel<<<NS / 64, 256>>>(S, Q, OH);
    knn_mma_kernel<<<NQ / 128, 512, SMEM_SZ>>>(out);
    cleanup_kernel<<<128, 256>>>(S, Q, out);
}